// round 17
// baseline (speedup 1.0000x reference)
#include <cuda_runtime.h>
#include <cstdint>

#define N_NODES 100000
#define N_EDGES 1600000
#define D 128

#define BUCKET_CAP 128   // max in-degree supported (Poisson(16): P(>=128) ~ 0)

// Scratch (allocation-free rule: __device__ globals)
__device__ float     g_h[(size_t)N_NODES * D];               // 51.2 MB
__device__ int       g_deg[N_NODES];
__device__ long long g_epack[(size_t)N_NODES * BUCKET_CAP];  // 102.4 MB

__device__ __forceinline__ uint32_t f2tf32(float f) {
    uint32_t u;
    asm("cvt.rna.tf32.f32 %0, %1;" : "=r"(u) : "f"(f));
    return u;
}

// ---------------------------------------------------------------------------
// edge_index dtype sniff (reference says int64; JAX w/o x64 emits int32)
// ---------------------------------------------------------------------------
__device__ __forceinline__ int sniff_is64(const void* ei_raw) {
    const long long* ei64 = (const long long*)ei_raw;
    int is64 = 1;
    #pragma unroll
    for (int i = 0; i < 4; i++) {
        long long v = __ldg(&ei64[i]);
        if (v < 0 || v >= N_NODES) is64 = 0;
    }
    return is64;
}
__device__ __forceinline__ int load_idx(const void* ei_raw, int is64, size_t pos) {
    if (is64) return (int)__ldg(&((const long long*)ei_raw)[pos]);
    return __ldg(&((const int*)ei_raw)[pos]);
}

// ---------------------------------------------------------------------------
// GEMM: g_h = x @ W via mma.sync.m16n8k8.tf32. CTA tile 64x128x128,
// SMEM 103.4 KB -> 2 CTAs/SM (stage of one overlaps MMA of the other).
// Also zeroes g_deg (64 counters per CTA) to save a separate launch.
// ---------------------------------------------------------------------------
#define TM 64
#define A_STRIDE 132
#define B_STRIDE 136
#define SMEM_GEMM ((TM * A_STRIDE + 128 * B_STRIDE) * 4)   // 103424 B

__global__ __launch_bounds__(256, 2) void gemm_mma_kernel(const float* __restrict__ x,
                                                          const float* __restrict__ W) {
    extern __shared__ uint32_t dsm[];
    uint32_t* As = dsm;                        // [64][132] tf32 bits (m,k)
    uint32_t* Bs = dsm + TM * A_STRIDE;        // [128][136] tf32 bits (k,n)

    const int tid = threadIdx.x;
    const int wid = tid >> 5;
    const int lane = tid & 31;
    const int r  = lane >> 2;                  // 0..7
    const int c4 = lane & 3;                   // 0..3
    const int m0 = blockIdx.x * TM;
    const int mrow = (wid >> 1) * 16;          // row-band within tile
    const int nt0 = (wid & 1) * 8;             // n-tile half

    // absorb zero_deg: each CTA clears its 64 counters (fill runs after gemm)
    if (tid < TM && m0 + tid < N_NODES) g_deg[m0 + tid] = 0;

    // --- Stage A (x tile, 64x128), convert to tf32: 2048 float4s ---
    #pragma unroll
    for (int it = 0; it < 8; it++) {
        int idx = it * 256 + tid;              // 0..2047
        int row = idx >> 5;                    // 0..63
        int q   = idx & 31;
        float4 v = make_float4(0.f, 0.f, 0.f, 0.f);
        if (m0 + row < N_NODES)
            v = *(const float4*)&x[(size_t)(m0 + row) * D + q * 4];
        uint4 u = make_uint4(f2tf32(v.x), f2tf32(v.y), f2tf32(v.z), f2tf32(v.w));
        *(uint4*)&As[row * A_STRIDE + q * 4] = u;
    }
    // --- Stage B (W, k-major, 128x128): 4096 float4s ---
    #pragma unroll
    for (int it = 0; it < 16; it++) {
        int idx = it * 256 + tid;
        int k  = idx >> 5;
        int q  = idx & 31;
        float4 v = *(const float4*)&W[(size_t)k * D + q * 4];
        uint4 u = make_uint4(f2tf32(v.x), f2tf32(v.y), f2tf32(v.z), f2tf32(v.w));
        *(uint4*)&Bs[k * B_STRIDE + q * 4] = u;
    }
    __syncthreads();

    float c[8][4];
    #pragma unroll
    for (int nt = 0; nt < 8; nt++)
        #pragma unroll
        for (int j = 0; j < 4; j++) c[nt][j] = 0.f;

    #pragma unroll 4
    for (int kk = 0; kk < 16; kk++) {
        const uint32_t* a_lo = &As[(mrow + r) * A_STRIDE + kk * 8 + c4];
        const uint32_t* a_hi = &As[(mrow + r + 8) * A_STRIDE + kk * 8 + c4];
        uint32_t a0 = a_lo[0];
        uint32_t a1 = a_hi[0];
        uint32_t a2 = a_lo[4];
        uint32_t a3 = a_hi[4];
        const uint32_t* b_lo = &Bs[(kk * 8 + c4) * B_STRIDE + r + nt0 * 8];
        const uint32_t* b_hi = b_lo + 4 * B_STRIDE;
        #pragma unroll
        for (int nt = 0; nt < 8; nt++) {
            uint32_t b0 = b_lo[nt * 8];
            uint32_t b1 = b_hi[nt * 8];
            asm volatile(
                "mma.sync.aligned.m16n8k8.row.col.f32.tf32.tf32.f32 "
                "{%0,%1,%2,%3}, {%4,%5,%6,%7}, {%8,%9}, {%0,%1,%2,%3};"
                : "+f"(c[nt][0]), "+f"(c[nt][1]), "+f"(c[nt][2]), "+f"(c[nt][3])
                : "r"(a0), "r"(a1), "r"(a2), "r"(a3), "r"(b0), "r"(b1));
        }
    }

    // --- Epilogue ---
    const int m_lo = m0 + mrow + r;
    const int m_hi = m_lo + 8;
    #pragma unroll
    for (int nt = 0; nt < 8; nt++) {
        int col = (nt0 + nt) * 8 + 2 * c4;
        if (m_lo < N_NODES)
            *(float2*)&g_h[(size_t)m_lo * D + col] = make_float2(c[nt][0], c[nt][1]);
        if (m_hi < N_NODES)
            *(float2*)&g_h[(size_t)m_hi * D + col] = make_float2(c[nt][2], c[nt][3]);
    }
}

// ---------------------------------------------------------------------------
// Fill buckets directly (deg zeroed inside gemm kernel).
// ---------------------------------------------------------------------------
__global__ __launch_bounds__(256) void fill_kernel(const void* __restrict__ ei_raw) {
    const int is64 = sniff_is64(ei_raw);
    int e = blockIdx.x * blockDim.x + threadIdx.x;
    if (e < N_EDGES) {
        int s = load_idx(ei_raw, is64, (size_t)e);
        int d = load_idx(ei_raw, is64, (size_t)N_EDGES + e);
        int pos = atomicAdd(&g_deg[d], 1);
        if (pos < BUCKET_CAP)
            g_epack[(size_t)d * BUCKET_CAP + pos] = ((long long)s << 32) | (unsigned)e;
    }
}

// ---------------------------------------------------------------------------
// Accumulate: one warp per destination node; 4-wide software pipeline with
// dual accumulators for MLP; byte-offset address math via shifts.
// ---------------------------------------------------------------------------
__device__ __forceinline__ float4 relu_add(float4 h, float4 e) {
    return make_float4(fmaxf(h.x + e.x, 0.f), fmaxf(h.y + e.y, 0.f),
                       fmaxf(h.z + e.z, 0.f), fmaxf(h.w + e.w, 0.f));
}

__global__ __launch_bounds__(256) void accumulate_kernel(const float* __restrict__ ea,
                                                         const float* __restrict__ bias,
                                                         float* __restrict__ out) {
    const int lane = threadIdx.x & 31;
    const int warp = (int)((blockIdx.x * blockDim.x + threadIdx.x) >> 5);
    const int nwarps = (int)((gridDim.x * blockDim.x) >> 5);
    const size_t lane_off = (size_t)lane * 16;        // byte offset of this lane's float4
    const char* hbase = (const char*)g_h + lane_off;
    const char* ebase = (const char*)ea + lane_off;

    for (int n = warp; n < N_NODES; n += nwarps) {
        int deg = __ldcs(&g_deg[n]);
        if (deg > BUCKET_CAP) deg = BUCKET_CAP;
        const long long* bucket = &g_epack[(size_t)n * BUCKET_CAP];

        float4 acc = __ldg(&((const float4*)bias)[lane]);
        float4 acc2 = make_float4(0.f, 0.f, 0.f, 0.f);

        int i = 0;
        for (; i + 4 <= deg; i += 4) {
            long long p0 = __ldcs(&bucket[i]);
            long long p1 = __ldcs(&bucket[i + 1]);
            long long p2 = __ldcs(&bucket[i + 2]);
            long long p3 = __ldcs(&bucket[i + 3]);

            // issue all 8 row loads before any arithmetic (MLP)
            float4 h0 = __ldg((const float4*)(hbase + ((p0 >> 32) << 9)));
            float4 h1 = __ldg((const float4*)(hbase + ((p1 >> 32) << 9)));
            float4 h2 = __ldg((const float4*)(hbase + ((p2 >> 32) << 9)));
            float4 h3 = __ldg((const float4*)(hbase + ((p3 >> 32) << 9)));
            float4 e0 = __ldcs((const float4*)(ebase + ((size_t)(unsigned)p0 << 9)));
            float4 e1 = __ldcs((const float4*)(ebase + ((size_t)(unsigned)p1 << 9)));
            float4 e2 = __ldcs((const float4*)(ebase + ((size_t)(unsigned)p2 << 9)));
            float4 e3 = __ldcs((const float4*)(ebase + ((size_t)(unsigned)p3 << 9)));

            float4 r0 = relu_add(h0, e0);
            float4 r1 = relu_add(h1, e1);
            float4 r2 = relu_add(h2, e2);
            float4 r3 = relu_add(h3, e3);
            acc.x += r0.x + r2.x;  acc.y += r0.y + r2.y;
            acc.z += r0.z + r2.z;  acc.w += r0.w + r2.w;
            acc2.x += r1.x + r3.x; acc2.y += r1.y + r3.y;
            acc2.z += r1.z + r3.z; acc2.w += r1.w + r3.w;
        }
        for (; i < deg; i++) {
            long long p = __ldcs(&bucket[i]);
            float4 hv = __ldg((const float4*)(hbase + ((p >> 32) << 9)));
            float4 ev = __ldcs((const float4*)(ebase + ((size_t)(unsigned)p << 9)));
            float4 r = relu_add(hv, ev);
            acc.x += r.x; acc.y += r.y; acc.z += r.z; acc.w += r.w;
        }

        acc.x += acc2.x; acc.y += acc2.y; acc.z += acc2.z; acc.w += acc2.w;
        // streaming store: out lines are dead after this — keep them out of L2
        __stcs((float4*)((char*)out + (size_t)n * 512 + lane_off), acc);
    }
}

// ---------------------------------------------------------------------------
extern "C" void kernel_launch(void* const* d_in, const int* in_sizes, int n_in,
                              void* d_out, int out_size) {
    (void)in_sizes; (void)n_in; (void)out_size;
    const float* x    = (const float*)d_in[0];
    const void*  ei   = d_in[1];
    const float* ea   = (const float*)d_in[2];
    const float* W    = (const float*)d_in[3];
    const float* bias = (const float*)d_in[4];
    float*       out  = (float*)d_out;

    cudaFuncSetAttribute(gemm_mma_kernel,
                         cudaFuncAttributeMaxDynamicSharedMemorySize, SMEM_GEMM);

    // h = x @ W  (tf32 mma.sync, 2 CTA/SM; also zeroes g_deg)
    gemm_mma_kernel<<<(N_NODES + TM - 1) / TM, 256, SMEM_GEMM>>>(x, W);

    // bucketed CSR-by-destination
    fill_kernel<<<(N_EDGES + 255) / 256, 256>>>(ei);

    // out[n] = bias + sum_{e: dst=n} relu(h[src_e] + ea[e])
    accumulate_kernel<<<12500, 256>>>(ea, bias, out);
}